// round 16
// baseline (speedup 1.0000x reference)
#include <cuda_runtime.h>
#include <cuda_bf16.h>
#include <math.h>
#include <stdint.h>

#define Bq 8
#define Nn 2048
#define Cc 256
#define Ee 32768
#define TOT (Bq*Nn*Cc)      // 4194304
#define Mr  (Bq*Nn)         // 16384

typedef __nv_bfloat16 bf16;

// Persistent scratch (device globals; no allocations allowed)
__device__ __align__(16) float g_h0[TOT];
__device__ __align__(16) float g_h1[TOT];
__device__ __align__(16) float g_tx1[TOT];
__device__ __align__(16) bf16  g_tx1_h[TOT], g_tx1_l[TOT];
__device__ __align__(16) bf16  g_tx2_h[TOT], g_tx2_l[TOT];
__device__ __align__(16) bf16  g_wch_h[3*3*Cc*Cc], g_wch_l[3*3*Cc*Cc];
__device__ __align__(16) bf16  g_wml_h[3*Cc*Cc],   g_wml_l[3*Cc*Cc];
__device__ float g_deg[3][Nn];
__device__ float g_norm[3][Ee];
__device__ float g_snorm[3][Nn];
__device__ float g_sred[14];       // 7 slots x {sum, sumsq}
__device__ int g_cnt[3][Nn];
__device__ int g_off[3][Nn + 1];
__device__ int g_ptr[3][Nn];
__device__ int g_csr[3][Ee];

__device__ __forceinline__ void split2(float x, bf16& h, bf16& l) {
    h = __float2bfloat16(x);
    l = __float2bfloat16(x - __bfloat162float(h));
}

// block-reduce (ls,lq) over blockDim.x threads (<=512) and atomically add into slot
__device__ __forceinline__ void stats_commit(float ls, float lq, int slot) {
    int lane = threadIdx.x & 31, wid = threadIdx.x >> 5;
    #pragma unroll
    for (int o = 16; o > 0; o >>= 1) {
        ls += __shfl_xor_sync(0xffffffffu, ls, o);
        lq += __shfl_xor_sync(0xffffffffu, lq, o);
    }
    __shared__ float ws[16], wq[16];
    if (lane == 0) { ws[wid] = ls; wq[wid] = lq; }
    __syncthreads();
    if (threadIdx.x == 0) {
        int nw = blockDim.x >> 5;
        float s = 0.f, q = 0.f;
        for (int i = 0; i < nw; i++) { s += ws[i]; q += wq[i]; }
        atomicAdd(&g_sred[slot * 2 + 0], s);
        atomicAdd(&g_sred[slot * 2 + 1], q);
    }
}

__device__ __forceinline__ void stats_fetch(int slot, float& m, float& r) {
    float s = g_sred[slot * 2 + 0], q = g_sred[slot * 2 + 1];
    m = s / (float)TOT;
    float var = q / (float)TOT - m * m;
    r = rsqrtf(var + 1e-5f);
}

// ---------------- init ----------------
__global__ void zero_sred() {
    if (threadIdx.x < 14) g_sred[threadIdx.x] = 0.f;
}

__global__ void copy_init(const float* __restrict__ x) {
    int i = blockIdx.x * 256 + threadIdx.x;
    float4 v = ((const float4*)x)[i];
    ((float4*)g_h0)[i] = v;
    float ls = (v.x + v.y) + (v.z + v.w);
    float lq = v.x*v.x + v.y*v.y + v.z*v.z + v.w*v.w;
    stats_commit(ls, lq, 0);
}

__global__ void split_w(const float* __restrict__ cw, const float* __restrict__ mw) {
    int i = blockIdx.x * 256 + threadIdx.x;
    int NC = 3 * 3 * Cc * Cc;
    if (i < NC) split2(cw[i], g_wch_h[i], g_wch_l[i]);
    if (i < 3 * Cc * Cc) split2(mw[i], g_wml_h[i], g_wml_l[i]);
}

// ---------------- CSR build ----------------
__global__ void zero_small3() {
    int i = blockIdx.x * 256 + threadIdx.x;
    if (i < 3 * Nn) {
        ((float*)g_deg)[i] = 0.f;
        ((float*)g_snorm)[i] = 0.f;
        ((int*)g_cnt)[i] = 0;
    }
}

__global__ void deg_count3(const int* __restrict__ ei, const float* __restrict__ ew) {
    int l = blockIdx.y;
    int e = blockIdx.x * 256 + threadIdx.x;
    const int* row = ei + l * 2 * Ee;
    const int* col = row + Ee;
    int r = row[e], c = col[e];
    float we = (r == c) ? 0.f : ew[l * Ee + e];
    atomicAdd(&g_deg[l][r], we);
    atomicAdd(&g_cnt[l][c], 1);
}

__global__ void scan3() {
    int l = blockIdx.x;
    __shared__ int chunk[256];
    int t = threadIdx.x;
    int base = t * 8;
    int s = 0;
    #pragma unroll
    for (int i = 0; i < 8; i++) s += g_cnt[l][base + i];
    chunk[t] = s;
    __syncthreads();
    for (int o = 1; o < 256; o <<= 1) {
        int v = (t >= o) ? chunk[t - o] : 0;
        __syncthreads();
        chunk[t] += v;
        __syncthreads();
    }
    int run = chunk[t] - s;
    #pragma unroll
    for (int i = 0; i < 8; i++) {
        g_off[l][base + i] = run;
        g_ptr[l][base + i] = run;
        run += g_cnt[l][base + i];
    }
    if (t == 255) g_off[l][Nn] = run;
}

__global__ void norm_scatter3(const int* __restrict__ ei, const float* __restrict__ ew) {
    int l = blockIdx.y;
    int e = blockIdx.x * 256 + threadIdx.x;
    const int* row = ei + l * 2 * Ee;
    const int* col = row + Ee;
    int r = row[e], c = col[e];
    float we = (r == c) ? 0.f : ew[l * Ee + e];
    float dr = g_deg[l][r], dc = g_deg[l][c];
    float ir = dr > 0.f ? rsqrtf(fmaxf(dr, 1e-12f)) : 0.f;
    float ic = dc > 0.f ? rsqrtf(fmaxf(dc, 1e-12f)) : 0.f;
    float nm = -(ir * we * ic);
    g_norm[l][e] = nm;
    atomicAdd(&g_snorm[l][c], nm);
    int pos = atomicAdd(&g_ptr[l][c], 1);
    g_csr[l][pos] = e;
}

// ---------------- sparse propagation ----------------
__global__ void prop_all(const int* __restrict__ row, int l, int slot, int first, int cur) {
    const float* hsrc = cur ? g_h1 : g_h0;
    int n = blockIdx.x;
    int b0 = blockIdx.y * 4;
    int t = threadIdx.x;
    int s = g_off[l][n], e = g_off[l][n + 1];
    float m, r;
    stats_fetch(slot, m, r);
    const float4* src = (const float4*)(first ? hsrc : g_tx1);
    float4 acc[4];
    #pragma unroll
    for (int b = 0; b < 4; b++) acc[b] = make_float4(0.f, 0.f, 0.f, 0.f);
    __shared__ int   sr[64];
    __shared__ float sn[64];
    for (int base = s; base < e; base += 64) {
        int cnt = min(64, e - base);
        if (t < cnt) {
            int eid = g_csr[l][base + t];
            sr[t] = row[eid];
            sn[t] = g_norm[l][eid];
        }
        __syncthreads();
        for (int j = 0; j < cnt; j++) {
            float nm = sn[j];
            const float4* rp = src + (size_t)sr[j] * 64 + t + (size_t)b0 * Nn * 64;
            #pragma unroll
            for (int b = 0; b < 4; b++) {
                float4 v = __ldg(rp + (size_t)b * Nn * 64);
                acc[b].x += nm * v.x; acc[b].y += nm * v.y;
                acc[b].z += nm * v.z; acc[b].w += nm * v.w;
            }
        }
        __syncthreads();
    }
    float sub = first ? (r * m * g_snorm[l][n]) : 0.f;
    #pragma unroll
    for (int b = 0; b < 4; b++) {
        size_t di = (size_t)((b0 + b) * Nn + n) * 64 + t;
        float4 o;
        bf16 *dh, *dl;
        if (first) {
            o.x = r * acc[b].x - sub; o.y = r * acc[b].y - sub;
            o.z = r * acc[b].z - sub; o.w = r * acc[b].w - sub;
            ((float4*)g_tx1)[di] = o;
            dh = g_tx1_h; dl = g_tx1_l;
        } else {
            float4 hv = __ldg(&((const float4*)hsrc)[di]);
            o.x = 2.f * acc[b].x - (hv.x - m) * r;
            o.y = 2.f * acc[b].y - (hv.y - m) * r;
            o.z = 2.f * acc[b].z - (hv.z - m) * r;
            o.w = 2.f * acc[b].w - (hv.w - m) * r;
            dh = g_tx2_h; dl = g_tx2_l;
        }
        __nv_bfloat162 h0, h1, l0, l1;
        split2(o.x, h0.x, l0.x); split2(o.y, h0.y, l0.y);
        split2(o.z, h1.x, l1.x); split2(o.w, h1.y, l1.y);
        ((__nv_bfloat162*)dh)[2*di] = h0;  ((__nv_bfloat162*)dh)[2*di+1] = h1;
        ((__nv_bfloat162*)dl)[2*di] = l0;  ((__nv_bfloat162*)dl)[2*di+1] = l1;
    }
}

// ---------------- tensor-core GEMM (bf16 split, inline LN, 3 passes/tile) ----------------
// 512 threads, 16 warps as 4x4, warp tile 32x32. Tile 128x128, grid (128, 2).
// Ping-pong h buffers: read h[cur], write h[1-cur].

#define GBM 128
#define GBN 128
#define GBK 64
#define APAD 72    // A rows: 64 + 8 bf16
#define BPAD 136   // B rows: 128 + 8 bf16

__device__ __forceinline__ uint32_t smem_u32(const void* p) {
    return (uint32_t)__cvta_generic_to_shared(p);
}
__device__ __forceinline__ void ldm_x4(uint32_t* r, uint32_t a) {
    asm volatile("ldmatrix.sync.aligned.m8n8.x4.shared.b16 {%0,%1,%2,%3}, [%4];"
                 : "=r"(r[0]), "=r"(r[1]), "=r"(r[2]), "=r"(r[3]) : "r"(a));
}
__device__ __forceinline__ void ldm_x4_t(uint32_t* r, uint32_t a) {
    asm volatile("ldmatrix.sync.aligned.m8n8.x4.trans.shared.b16 {%0,%1,%2,%3}, [%4];"
                 : "=r"(r[0]), "=r"(r[1]), "=r"(r[2]), "=r"(r[3]) : "r"(a));
}
__device__ __forceinline__ void mma16816(float* d, const uint32_t* a, const uint32_t* b) {
    asm volatile("mma.sync.aligned.m16n8k16.row.col.f32.bf16.bf16.f32 "
                 "{%0,%1,%2,%3},{%4,%5,%6,%7},{%8,%9},{%0,%1,%2,%3};"
                 : "+f"(d[0]), "+f"(d[1]), "+f"(d[2]), "+f"(d[3])
                 : "r"(a[0]), "r"(a[1]), "r"(a[2]), "r"(a[3]), "r"(b[0]), "r"(b[1]));
}

__device__ __forceinline__ float gelu_exact(float v) {
    return 0.5f * v * (1.f + erff(v * 0.70710678118654752f));
}

template<int MODE>
__device__ __forceinline__ void stage_ptrs(int s, int l, int& seg, int& kc,
                                           const bf16*& Ah, const bf16*& Al,
                                           const bf16*& Wh, const bf16*& Wl) {
    seg = (MODE == 0) ? (s >> 2) : 0;
    kc = s & 3;
    if (seg == 1) { Ah = g_tx1_h; Al = g_tx1_l; }
    else if (seg == 2) { Ah = g_tx2_h; Al = g_tx2_l; }
    else { Ah = nullptr; Al = nullptr; }
    if (MODE == 0) {
        Wh = g_wch_h + (size_t)(l * 3 + seg) * Cc * Cc;
        Wl = g_wch_l + (size_t)(l * 3 + seg) * Cc * Cc;
    } else {
        Wh = g_wml_h + (size_t)l * Cc * Cc;
        Wl = g_wml_l + (size_t)l * Cc * Cc;
    }
}

template<int MODE>
__global__ __launch_bounds__(512, 1) void tc_gemm(int l, const float* __restrict__ bias,
                                                  int slotIn, int slotOut, int cur) {
    const float* hin = cur ? g_h1 : g_h0;
    float* hout = cur ? g_h0 : g_h1;

    extern __shared__ __align__(16) char smem_raw[];
    bf16 (*As_h)[APAD] = (bf16 (*)[APAD])smem_raw;                               // [128][72]
    bf16 (*As_l)[APAD] = (bf16 (*)[APAD])(smem_raw + GBM*APAD*2);                // [128][72]
    bf16 (*Bs_h)[BPAD] = (bf16 (*)[BPAD])(smem_raw + 2*GBM*APAD*2);              // [64][136]
    bf16 (*Bs_l)[BPAD] = (bf16 (*)[BPAD])(smem_raw + 2*GBM*APAD*2 + GBK*BPAD*2); // [64][136]

    const int m0 = blockIdx.x * GBM, n0 = blockIdx.y * GBN;
    const int tid = threadIdx.x;
    const int wid = tid >> 5, lane = tid & 31;
    const int wm = wid >> 2, wn = wid & 3;           // 4x4 warps; warp tile 32x32
    const int lrow = lane & 15, lsel = lane >> 4;

    const int NST = (MODE == 0) ? 12 : 4;

    float m, r;
    stats_fetch(slotIn, m, r);

    float acc[2][4][4] = {};
    uint4 pa[4], pb[4];

#define LOAD_STAGE(S)                                                                 \
    {                                                                                 \
        int seg, kc; const bf16 *Ah_, *Al_, *Wh_, *Wl_;                               \
        stage_ptrs<MODE>((S), l, seg, kc, Ah_, Al_, Wh_, Wl_);                        \
        if (seg == 0) {                                                               \
            _Pragma("unroll")                                                         \
            for (int p = 0; p < 4; p++) {                                             \
                int ci = tid + p * 512;                                               \
                int row = ci >> 4, c4 = (ci & 15) * 4;                                \
                pa[p] = *(const uint4*)(hin + (size_t)(m0 + row) * Cc + kc * GBK + c4); \
            }                                                                         \
        } else {                                                                      \
            _Pragma("unroll")                                                         \
            for (int p = 0; p < 2; p++) {                                             \
                int ci = tid + p * 512;                                               \
                int row = ci >> 3, c8 = (ci & 7) * 8;                                 \
                pa[p]     = *(const uint4*)(Ah_ + (size_t)(m0 + row) * Cc + kc * GBK + c8); \
                pa[p + 2] = *(const uint4*)(Al_ + (size_t)(m0 + row) * Cc + kc * GBK + c8); \
            }                                                                         \
        }                                                                             \
        _Pragma("unroll")                                                             \
        for (int p = 0; p < 2; p++) {                                                 \
            int ci = tid + p * 512;                                                   \
            int row = ci >> 4, c8 = (ci & 15) * 8;                                    \
            pb[p]     = *(const uint4*)(Wh_ + (size_t)(kc * GBK + row) * Cc + n0 + c8); \
            pb[p + 2] = *(const uint4*)(Wl_ + (size_t)(kc * GBK + row) * Cc + n0 + c8); \
        }                                                                             \
    }

#define STORE_STAGE(S)                                                                \
    {                                                                                 \
        int seg = (MODE == 0) ? ((S) >> 2) : 0;                                       \
        if (seg == 0) {                                                               \
            _Pragma("unroll")                                                         \
            for (int p = 0; p < 4; p++) {                                             \
                int ci = tid + p * 512;                                               \
                int row = ci >> 4, c4 = (ci & 15) * 4;                                \
                float4 v = *(float4*)&pa[p];                                          \
                bf16 hh[4], ll[4];                                                    \
                split2((v.x - m) * r, hh[0], ll[0]);                                  \
                split2((v.y - m) * r, hh[1], ll[1]);                                  \
                split2((v.z - m) * r, hh[2], ll[2]);                                  \
                split2((v.w - m) * r, hh[3], ll[3]);                                  \
                *(uint2*)&As_h[row][c4] = *(uint2*)hh;                                \
                *(uint2*)&As_l[row][c4] = *(uint2*)ll;                                \
            }                                                                         \
        } else {                                                                      \
            _Pragma("unroll")                                                         \
            for (int p = 0; p < 2; p++) {                                             \
                int ci = tid + p * 512;                                               \
                int row = ci >> 3, c8 = (ci & 7) * 8;                                 \
                *(uint4*)&As_h[row][c8] = pa[p];                                      \
                *(uint4*)&As_l[row][c8] = pa[p + 2];                                  \
            }                                                                         \
        }                                                                             \
        _Pragma("unroll")                                                             \
        for (int p = 0; p < 2; p++) {                                                 \
            int ci = tid + p * 512;                                                   \
            int row = ci >> 4, c8 = (ci & 15) * 8;                                    \
            *(uint4*)&Bs_h[row][c8] = pb[p];                                          \
            *(uint4*)&Bs_l[row][c8] = pb[p + 2];                                      \
        }                                                                             \
    }

    LOAD_STAGE(0);
    STORE_STAGE(0);
    __syncthreads();

    for (int s = 0; s < NST; s++) {
        if (s + 1 < NST) LOAD_STAGE(s + 1);
        #pragma unroll
        for (int ks = 0; ks < 4; ks++) {
            uint32_t ah[2][4], al[2][4], wh[2][4], wl[2][4];
            #pragma unroll
            for (int mt = 0; mt < 2; mt++) {
                ldm_x4(ah[mt], smem_u32(&As_h[wm * 32 + mt * 16 + lrow][ks * 16 + lsel * 8]));
                ldm_x4(al[mt], smem_u32(&As_l[wm * 32 + mt * 16 + lrow][ks * 16 + lsel * 8]));
            }
            #pragma unroll
            for (int f = 0; f < 2; f++) {
                ldm_x4_t(wh[f], smem_u32(&Bs_h[ks * 16 + lrow][wn * 32 + f * 16 + lsel * 8]));
                ldm_x4_t(wl[f], smem_u32(&Bs_l[ks * 16 + lrow][wn * 32 + f * 16 + lsel * 8]));
            }
            #pragma unroll
            for (int mt = 0; mt < 2; mt++)
                #pragma unroll
                for (int nt = 0; nt < 4; nt++) {
                    mma16816(acc[mt][nt], ah[mt], &wh[nt >> 1][(nt & 1) * 2]);
                    mma16816(acc[mt][nt], al[mt], &wh[nt >> 1][(nt & 1) * 2]);
                    mma16816(acc[mt][nt], ah[mt], &wl[nt >> 1][(nt & 1) * 2]);
                }
        }
        __syncthreads();
        if (s + 1 < NST) {
            STORE_STAGE(s + 1);
            __syncthreads();
        }
    }

    // epilogue: hout = hin + ... ; accumulate LN stats of the NEW h into slotOut
    float ls = 0.f, lq = 0.f;
    const int grp = lane >> 2, qc = lane & 3;
    #pragma unroll
    for (int mt = 0; mt < 2; mt++) {
        #pragma unroll
        for (int nt = 0; nt < 4; nt++) {
            int r0 = m0 + wm * 32 + mt * 16 + grp;
            int c0 = n0 + wn * 32 + nt * 8 + qc * 2;
            float b0 = bias[c0], b1 = bias[c0 + 1];
            #pragma unroll
            for (int hh = 0; hh < 2; hh++) {
                int rr = r0 + hh * 8;
                size_t off = (size_t)rr * Cc + c0;
                float2 hv = *(const float2*)(hin + off);
                float v0 = acc[mt][nt][hh * 2 + 0] + b0;
                float v1 = acc[mt][nt][hh * 2 + 1] + b1;
                if (MODE == 0) { hv.x += v0; hv.y += v1; }
                else           { hv.x += gelu_exact(v0); hv.y += gelu_exact(v1); }
                *(float2*)(hout + off) = hv;
                ls += hv.x + hv.y;
                lq += hv.x * hv.x + hv.y * hv.y;
            }
        }
    }
    stats_commit(ls, lq, slotOut);
}

// ---------------- final mean over nodes ----------------
__global__ void zero_out(float* __restrict__ out) {
    int i = blockIdx.x * 256 + threadIdx.x;
    if (i < Bq * Cc) out[i] = 0.f;
}

__global__ void mean_k(float* __restrict__ out) {
    int b = blockIdx.x, chunk = blockIdx.y;
    int c = threadIdx.x;
    float s = 0.f;
    int nb = chunk * 128;
    const float* base = g_h0 + (size_t)b * Nn * Cc + c;
    for (int n = nb; n < nb + 128; n++) s += base[(size_t)n * Cc];
    atomicAdd(&out[b * Cc + c], s * (1.f / (float)Nn));
}

// ---------------- launch ----------------
extern "C" void kernel_launch(void* const* d_in, const int* in_sizes, int n_in,
                              void* d_out, int out_size) {
    const float* nf = (const float*)d_in[0];   // node_feature [8,2048,256]
    const float* ew = (const float*)d_in[1];   // edge_weight  [3,32768]
    const float* cw = (const float*)d_in[2];   // cheb_w [3,3,256,256]
    const float* cb = (const float*)d_in[3];   // cheb_b [3,256]
    const float* mw = (const float*)d_in[4];   // mlp_w  [3,256,256]
    const float* mb = (const float*)d_in[5];   // mlp_b  [3,256]
    const int*   ei = (const int*)d_in[6];     // edge_index [3,2,32768]
    float* out = (float*)d_out;                // [8,256]

    const int SMEM = 2 * GBM * APAD * 2 + 2 * GBK * BPAD * 2;   // 71680 B
    cudaFuncSetAttribute(tc_gemm<0>, cudaFuncAttributeMaxDynamicSharedMemorySize, SMEM);
    cudaFuncSetAttribute(tc_gemm<1>, cudaFuncAttributeMaxDynamicSharedMemorySize, SMEM);

    zero_sred<<<1, 32>>>();
    copy_init<<<TOT / 1024, 256>>>(nf);        // h -> g_h0, stats -> slot 0
    split_w<<<(3 * 3 * Cc * Cc + 255) / 256, 256>>>(cw, mw);

    zero_small3<<<(3 * Nn + 255) / 256, 256>>>();
    deg_count3<<<dim3(Ee / 256, 3), 256>>>(ei, ew);
    scan3<<<3, 256>>>();
    norm_scatter3<<<dim3(Ee / 256, 3), 256>>>(ei, ew);

    int cur = 0;
    for (int l = 0; l < 3; l++) {
        const int* row = ei + l * 2 * Ee;
        int slotA = 2 * l, slotB = 2 * l + 1, slotC = 2 * l + 2;

        prop_all<<<dim3(Nn, 2), 64>>>(row, l, slotA, 1, cur);   // tx1
        prop_all<<<dim3(Nn, 2), 64>>>(row, l, slotA, 0, cur);   // tx2

        tc_gemm<0><<<dim3(Mr / GBM, Cc / GBN), 512, SMEM>>>(l, cb + l * Cc, slotA, slotB, cur);
        cur ^= 1;
        tc_gemm<1><<<dim3(Mr / GBM, Cc / GBN), 512, SMEM>>>(l, mb + l * Cc, slotB, slotC, cur);
        cur ^= 1;
    }
    zero_out<<<8, 256>>>(out);
    mean_k<<<dim3(Bq, 16), 256>>>(out);
}